// round 13
// baseline (speedup 1.0000x reference)
#include <cuda_runtime.h>
#include <cuda_bf16.h>
#include <cstdint>

// Problem constants (fixed by the reference)
#define NB   1024      // batch
#define NS1  25        // hop-1 fanout
#define NS2  10        // hop-2 fanout
#define ND   256       // feature dim
#define NH   128       // per-branch hidden
#define NC   64        // classes
#define M1   (NB*NS1)  // 25600
#define NM1B (M1/4)    // 6400 hop-2 mean blocks (4 groups each)
#define NM0B (NB/4)    // 256 hop-1 mean blocks
#define NMEANB (NM1B + NM0B)   // 6656

typedef unsigned long long ull;

// Scratch (no cudaMalloc allowed -> __device__ globals)
__device__ float g_m1[M1 * ND];    // mean over S2 of hop-2 feats  [25600,256]
__device__ float g_m0[NB * ND];    // mean over S1 of hop-1 feats  [1024,256]
__device__ float g_g1[M1 * ND];    // layer-1 out, hop-1 set       [25600,256]
__device__ float g_g0[NB * ND];    // layer-1 out, batch set       [1024,256]
__device__ float g_Wc[512 * NC];   // collapsed layer2*head weights[512,64]
__device__ float g_bc[NC];         // collapsed bias               [64]
__device__ float g_Wx1T[NH * ND];  // Wx1^T  [128,256]
__device__ float g_Wn1T[NH * ND];  // Wn1^T  [128,256]

// ---- tf32 helpers (baseline sm_80 PTX; legal on compute_103) ---------------
__device__ __forceinline__ uint4 tf32x4(float4 v) {
    uint4 u;
    asm("cvt.rna.tf32.f32 %0, %1;" : "=r"(u.x) : "f"(v.x));
    asm("cvt.rna.tf32.f32 %0, %1;" : "=r"(u.y) : "f"(v.y));
    asm("cvt.rna.tf32.f32 %0, %1;" : "=r"(u.z) : "f"(v.z));
    asm("cvt.rna.tf32.f32 %0, %1;" : "=r"(u.w) : "f"(v.w));
    return u;
}
#define MMA_TF32(d, a, b)                                                  \
    asm volatile("mma.sync.aligned.m16n8k8.row.col.f32.tf32.tf32.f32 "    \
        "{%0,%1,%2,%3}, {%4,%5,%6,%7}, {%8,%9}, {%0,%1,%2,%3};"           \
        : "+f"((d)[0]), "+f"((d)[1]), "+f"((d)[2]), "+f"((d)[3])          \
        : "r"((a)[0]), "r"((a)[1]), "r"((a)[2]), "r"((a)[3]),             \
          "r"((b)[0]), "r"((b)[1]))

// ---- cp.async (baseline sm_80) ---------------------------------------------
#define CP_ASYNC16(saddr, gptr)                                            \
    asm volatile("cp.async.cg.shared.global [%0], [%1], 16;"               \
                 :: "r"(saddr), "l"(gptr) : "memory")
#define CP_COMMIT() asm volatile("cp.async.commit_group;" ::: "memory")
#define CP_WAIT0()  asm volatile("cp.async.wait_group 0;" ::: "memory")

// ---------------------------------------------------------------------------
// Simple gather-mean (LDG path) for small F=25 set.
// ---------------------------------------------------------------------------
template<int F, bool HAS_IDS>
__device__ __forceinline__ void mean_body(
    const float* __restrict__ src, const int* __restrict__ ids,
    float* __restrict__ dst, int g)
{
    const int c = (threadIdx.x & 63) * 4;
    const long base = (long)g * F;
    int rows[F];
    #pragma unroll
    for (int s = 0; s < F; ++s)
        rows[s] = HAS_IDS ? ids[base + s] : (int)(base + s);
    float4 acc = make_float4(0.f, 0.f, 0.f, 0.f);
    #pragma unroll
    for (int s = 0; s < F; ++s) {
        float4 u = *(const float4*)&src[(size_t)rows[s] * ND + c];
        acc.x += u.x; acc.y += u.y; acc.z += u.z; acc.w += u.w;
    }
    constexpr float inv = 1.0f / (float)F;
    acc.x *= inv; acc.y *= inv; acc.z *= inv; acc.w *= inv;
    __stcs((float4*)&dst[(size_t)g * ND + c], acc);
}

// ---------------------------------------------------------------------------
// means + Wc/bc + W^T precompute. Grid = NMEANB + 35.
//   blocks [0, NM1B):        m1 via cp.async staging (4 groups/block, F=10)
//   blocks [NM1B, NMEANB):   m0 via LDG path (4 groups/block, F=25)
//   +32 Wc | +1 bc | +2 W^T
// ---------------------------------------------------------------------------
__global__ void __launch_bounds__(256) means_kernel(
    const float* __restrict__ feat,
    const int* __restrict__ ids1, const int* __restrict__ ids2,
    const float* __restrict__ Wx1, const float* __restrict__ Wn1,
    const float* __restrict__ Wx2, const float* __restrict__ bx2,
    const float* __restrict__ Wn2, const float* __restrict__ bn2,
    const float* __restrict__ Wfc, const float* __restrict__ bfc,
    float* __restrict__ m1, float* __restrict__ m0,
    float* __restrict__ Wc, float* __restrict__ bc,
    float* __restrict__ Wx1T, float* __restrict__ Wn1T)
{
    __shared__ float4 stage[4][NS2][64];   // 40 KB: 4 groups x 10 rows x 1KB
    const int bx = blockIdx.x;
    const int t  = threadIdx.x;

    if (bx < NM1B) {
        // ---- hop-2 mean via cp.async: registers never block the gather ----
        const int lg = t >> 6;             // lane group 0..3 -> group
        const int ln = t & 63;             // column slot (16B each)
        const int g  = bx * 4 + lg;
        const long base = (long)g * NS2;
        #pragma unroll
        for (int s = 0; s < NS2; ++s) {
            const int row = ids2[base + s];
            const uint32_t sa =
                (uint32_t)__cvta_generic_to_shared(&stage[lg][s][ln]);
            CP_ASYNC16(sa, &feat[(size_t)row * ND + ln * 4]);
        }
        CP_COMMIT();
        CP_WAIT0();                        // own writes only -> no barrier
        float4 acc = make_float4(0.f, 0.f, 0.f, 0.f);
        #pragma unroll
        for (int s = 0; s < NS2; ++s) {
            float4 u = stage[lg][s][ln];
            acc.x += u.x; acc.y += u.y; acc.z += u.z; acc.w += u.w;
        }
        constexpr float inv = 1.0f / (float)NS2;
        acc.x *= inv; acc.y *= inv; acc.z *= inv; acc.w *= inv;
        __stcs((float4*)&m1[(size_t)g * ND + ln * 4], acc);
    } else if (bx < NMEANB) {
        mean_body<NS1, true>(feat, ids1, m0, (bx - NM1B) * 4 + (t >> 6));
    } else if (bx < NMEANB + 32) {
        const int R0 = (bx - NMEANB) * 16;
        const int c  = t & 63;
        const int rg = t >> 6;
        const bool top = (R0 < 256);
        const float* W2   = top ? Wx2 : Wn2;
        const float* WfcH = Wfc + (top ? 0 : 128 * NC);
        const int rbase = (top ? R0 : R0 - 256) + rg * 4;
        float acc[4] = {0.f, 0.f, 0.f, 0.f};
        #pragma unroll 8
        for (int k = 0; k < 128; ++k) {
            float w = WfcH[(size_t)k * NC + c];
            #pragma unroll
            for (int i = 0; i < 4; ++i)
                acc[i] = fmaf(W2[(size_t)(rbase + i) * NH + k], w, acc[i]);
        }
        #pragma unroll
        for (int i = 0; i < 4; ++i)
            Wc[(size_t)(R0 + rg * 4 + i) * NC + c] = acc[i];
    } else if (bx == NMEANB + 32) {
        if (t < NC) {
            float acc = bfc[t];
            #pragma unroll 8
            for (int k = 0; k < 128; ++k) {
                acc = fmaf(bx2[k], Wfc[(size_t)k * NC + t], acc);
                acc = fmaf(bn2[k], Wfc[(size_t)(128 + k) * NC + t], acc);
            }
            bc[t] = acc;
        }
    } else {
        const float* W = (bx == NMEANB + 33) ? Wx1 : Wn1;
        float* WT      = (bx == NMEANB + 33) ? Wx1T : Wn1T;
        for (int idx = t; idx < ND * NH; idx += 256) {
            int k = idx >> 7, n = idx & 127;
            WT[(size_t)n * ND + k] = W[idx];
        }
    }
}

// ---------------------------------------------------------------------------
// Layer 1 via mma.sync tf32 (R9-proven single-buffer version). Grid 416.
// CTA tile 128x128, K=256 in 8 chunks of 32. 8 warps: warp = 64m x 32n,
// 4x4 frags of m16n8k8. Smem rows stride 36 words (conflict-free LDS).
// ---------------------------------------------------------------------------
__global__ void __launch_bounds__(256, 2) layer1_mma(
    const float* __restrict__ feat,
    const int* __restrict__ ids0, const int* __restrict__ ids1,
    const float* __restrict__ m1, const float* __restrict__ m0,
    const float* __restrict__ Wx1T, const float* __restrict__ bx1,
    const float* __restrict__ Wn1T, const float* __restrict__ bn1,
    float* __restrict__ g1, float* __restrict__ g0)
{
    __shared__ uint32_t As[128 * 36];   // 18KB, [row][k] stride 36
    __shared__ uint32_t Bs[128 * 36];   // 18KB, [n][k]  stride 36

    // branch decode
    const float* Asrc; const int* ids; const float* WT; const float* bias;
    float* C; int colOff, mbase;
    const int x = blockIdx.x;
    if (x < 200)      { Asrc = feat; ids = ids1; WT = Wx1T; bias = bx1; C = g1; colOff = 0;   mbase = x * 128; }
    else if (x < 400) { Asrc = m1;   ids = 0;    WT = Wn1T; bias = bn1; C = g1; colOff = 128; mbase = (x - 200) * 128; }
    else if (x < 408) { Asrc = feat; ids = ids0; WT = Wx1T; bias = bx1; C = g0; colOff = 0;   mbase = (x - 400) * 128; }
    else              { Asrc = m0;   ids = 0;    WT = Wn1T; bias = bn1; C = g0; colOff = 128; mbase = (x - 408) * 128; }

    const int t    = threadIdx.x;
    const int r    = t >> 1;            // staging row 0..127
    const int kh   = (t & 1) * 16;      // staging k half
    const int arow = ids ? ids[mbase + r] : (mbase + r);
    const float* ap = Asrc + (size_t)arow * ND + kh;
    const float* bp = WT + (size_t)r * ND + kh;
    uint32_t* Ad = &As[r * 36 + kh];
    uint32_t* Bd = &Bs[r * 36 + kh];

    const int wid = t >> 5, lane = t & 31;
    const int g = lane >> 2, c = lane & 3;
    const int m0w = (wid & 1) * 64;
    const int n0w = (wid >> 1) * 32;

    float acc[4][4][4];
    #pragma unroll
    for (int mf = 0; mf < 4; ++mf)
        #pragma unroll
        for (int nf = 0; nf < 4; ++nf)
            #pragma unroll
            for (int i = 0; i < 4; ++i) acc[mf][nf][i] = 0.f;

    #pragma unroll 1
    for (int ch = 0; ch < 8; ++ch) {
        const int k0 = ch * 32;
        float4 av0 = *(const float4*)(ap + k0);
        float4 av1 = *(const float4*)(ap + k0 + 4);
        float4 av2 = *(const float4*)(ap + k0 + 8);
        float4 av3 = *(const float4*)(ap + k0 + 12);
        float4 bv0 = *(const float4*)(bp + k0);
        float4 bv1 = *(const float4*)(bp + k0 + 4);
        float4 bv2 = *(const float4*)(bp + k0 + 8);
        float4 bv3 = *(const float4*)(bp + k0 + 12);
        if (ch) __syncthreads();
        *(uint4*)(Ad + 0)  = tf32x4(av0);
        *(uint4*)(Ad + 4)  = tf32x4(av1);
        *(uint4*)(Ad + 8)  = tf32x4(av2);
        *(uint4*)(Ad + 12) = tf32x4(av3);
        *(uint4*)(Bd + 0)  = tf32x4(bv0);
        *(uint4*)(Bd + 4)  = tf32x4(bv1);
        *(uint4*)(Bd + 8)  = tf32x4(bv2);
        *(uint4*)(Bd + 12) = tf32x4(bv3);
        __syncthreads();

        #pragma unroll
        for (int kb = 0; kb < 32; kb += 8) {
            uint32_t a[4][4], b[4][2];
            #pragma unroll
            for (int mf = 0; mf < 4; ++mf) {
                const int base = (m0w + mf * 16 + g) * 36 + kb + c;
                a[mf][0] = As[base];
                a[mf][1] = As[base + 8 * 36];
                a[mf][2] = As[base + 4];
                a[mf][3] = As[base + 8 * 36 + 4];
            }
            #pragma unroll
            for (int nf = 0; nf < 4; ++nf) {
                const int bb = (n0w + nf * 8 + g) * 36 + kb + c;
                b[nf][0] = Bs[bb];
                b[nf][1] = Bs[bb + 4];
            }
            #pragma unroll
            for (int mf = 0; mf < 4; ++mf)
                #pragma unroll
                for (int nf = 0; nf < 4; ++nf)
                    MMA_TF32(acc[mf][nf], a[mf], b[nf]);
        }
    }

    // epilogue: bias + relu, st.v2 per frag row
    #pragma unroll
    for (int nf = 0; nf < 4; ++nf) {
        const int bcol = n0w + nf * 8 + c * 2;
        const float b0 = bias[bcol], b1 = bias[bcol + 1];
        #pragma unroll
        for (int mf = 0; mf < 4; ++mf) {
            const int m = mbase + m0w + mf * 16 + g;
            float2 v0 = make_float2(fmaxf(acc[mf][nf][0] + b0, 0.f),
                                    fmaxf(acc[mf][nf][1] + b1, 0.f));
            float2 v1 = make_float2(fmaxf(acc[mf][nf][2] + b0, 0.f),
                                    fmaxf(acc[mf][nf][3] + b1, 0.f));
            *(float2*)&C[(size_t)m * ND + colOff + bcol]       = v0;
            *(float2*)&C[(size_t)(m + 8) * ND + colOff + bcol] = v1;
        }
    }
}

// ---------------------------------------------------------------------------
// Final GEMM with fused g1-mean: out[1024,64] = [g0 | mean25(g1)] @ Wc + bc.
// grid 128, 8-row tiles. gm slice computed in-kernel (no gm buffer/launch).
// ---------------------------------------------------------------------------
__global__ void __launch_bounds__(256) final_kernel(
    const float* __restrict__ g0, const float* __restrict__ g1,
    const float* __restrict__ Wc, const float* __restrict__ bc,
    float* __restrict__ out)
{
    __shared__ float As[8 * 520];      // [row][k 0..511], pad 8
    __shared__ float Ws[64 * 68];      // [k][c], pad 4

    const int t  = threadIdx.x;
    const int m0 = blockIdx.x * 8;

    // ---- stage g0 half: 8 rows x 256 k ----
    #pragma unroll
    for (int i = 0; i < 2; ++i) {
        int s = t + 256 * i;                 // 512 float4 slots
        int row = s >> 6, k4 = (s & 63) * 4;
        *(float4*)&As[row * 520 + k4] =
            *(const float4*)&g0[(size_t)(m0 + row) * ND + k4];
    }
    // ---- compute gm half: thread covers 2 groups x one float4 column ----
    {
        const int c4 = (t & 63) * 4;
        const int gs = t >> 6;               // 0..3
        #pragma unroll
        for (int h = 0; h < 2; ++h) {
            const int grp = gs + 4 * h;
            const float* src = g1 + (size_t)(m0 + grp) * NS1 * ND + c4;
            float4 acc = make_float4(0.f, 0.f, 0.f, 0.f);
            #pragma unroll
            for (int s = 0; s < NS1; ++s) {
                float4 u = *(const float4*)(src + (size_t)s * ND);
                acc.x += u.x; acc.y += u.y; acc.z += u.z; acc.w += u.w;
            }
            constexpr float inv = 1.0f / (float)NS1;
            acc.x *= inv; acc.y *= inv; acc.z *= inv; acc.w *= inv;
            *(float4*)&As[grp * 520 + 256 + c4] = acc;
        }
    }
    // ---- prefetch Wc chunk 0 ----
    float4 breg[4];
    #pragma unroll
    for (int i = 0; i < 4; ++i) {
        int s = t + 256 * i;
        int kk = s >> 4, c4 = (s & 15) * 4;
        breg[i] = *(const float4*)&Wc[(size_t)kk * NC + c4];
    }
    __syncthreads();

    const int c  = t & 63;
    const int r0 = (t >> 6) * 2;
    float acc0 = 0.f, acc1 = 0.f;

    #pragma unroll 1
    for (int j = 0; j < 8; ++j) {
        #pragma unroll
        for (int i = 0; i < 4; ++i) {
            int s = t + 256 * i;
            int kk = s >> 4, c4 = (s & 15) * 4;
            *(float4*)&Ws[kk * 68 + c4] = breg[i];
        }
        __syncthreads();
        if (j < 7) {
            #pragma unroll
            for (int i = 0; i < 4; ++i) {
                int s = t + 256 * i;
                int kk = (s >> 4) + (j + 1) * 64, c4 = (s & 15) * 4;
                breg[i] = *(const float4*)&Wc[(size_t)kk * NC + c4];
            }
        }
        const float* a0p = &As[r0 * 520 + j * 64];
        const float* a1p = &As[(r0 + 1) * 520 + j * 64];
        #pragma unroll
        for (int k = 0; k < 64; ++k) {
            float w = Ws[k * 68 + c];
            acc0 = fmaf(a0p[k], w, acc0);
            acc1 = fmaf(a1p[k], w, acc1);
        }
        __syncthreads();
    }

    float b = bc[c];
    out[(size_t)(m0 + r0) * NC + c]     = acc0 + b;
    out[(size_t)(m0 + r0 + 1) * NC + c] = acc1 + b;
}

// ---------------------------------------------------------------------------
extern "C" void kernel_launch(void* const* d_in, const int* in_sizes, int n_in,
                              void* d_out, int out_size)
{
    const int*   ids0 = (const int*)  d_in[0];
    const int*   ids1 = (const int*)  d_in[1];
    const int*   ids2 = (const int*)  d_in[2];
    const float* feat = (const float*)d_in[3];
    const float* Wx1  = (const float*)d_in[4];
    const float* bx1  = (const float*)d_in[5];
    const float* Wn1  = (const float*)d_in[6];
    const float* bn1  = (const float*)d_in[7];
    const float* Wx2  = (const float*)d_in[8];
    const float* bx2  = (const float*)d_in[9];
    const float* Wn2  = (const float*)d_in[10];
    const float* bn2  = (const float*)d_in[11];
    const float* Wfc  = (const float*)d_in[12];
    const float* bfc  = (const float*)d_in[13];
    float* out = (float*)d_out;

    float *m1, *m0, *g1, *g0, *Wc, *bc, *Wx1T, *Wn1T;
    cudaGetSymbolAddress((void**)&m1, g_m1);
    cudaGetSymbolAddress((void**)&m0, g_m0);
    cudaGetSymbolAddress((void**)&g1, g_g1);
    cudaGetSymbolAddress((void**)&g0, g_g0);
    cudaGetSymbolAddress((void**)&Wc, g_Wc);
    cudaGetSymbolAddress((void**)&bc, g_bc);
    cudaGetSymbolAddress((void**)&Wx1T, g_Wx1T);
    cudaGetSymbolAddress((void**)&Wn1T, g_Wn1T);

    // 1) gather means (hop-2 via cp.async staging) + Wc/bc/W^T precompute
    means_kernel<<<NMEANB + 35, 256>>>(
        feat, ids1, ids2, Wx1, Wn1, Wx2, bx2, Wn2, bn2, Wfc, bfc,
        m1, m0, Wc, bc, Wx1T, Wn1T);

    // 2) layer 1: four branch GEMMs on tf32 tensor cores
    layer1_mma<<<416, 256>>>(
        feat, ids0, ids1, m1, m0, Wx1T, bx1, Wn1T, bn1, g1, g0);

    // 3) fused g1-mean + collapsed layer2+head GEMM
    final_kernel<<<NB / 8, 256>>>(g0, g1, Wc, bc, out);
}

// round 14
// speedup vs baseline: 1.0054x; 1.0054x over previous
#include <cuda_runtime.h>
#include <cuda_bf16.h>
#include <cstdint>

// Problem constants (fixed by the reference)
#define NB   1024      // batch
#define NS1  25        // hop-1 fanout
#define NS2  10        // hop-2 fanout
#define ND   256       // feature dim
#define NH   128       // per-branch hidden
#define NC   64        // classes
#define M1   (NB*NS1)  // 25600
#define NMEAN2 (M1/8 + NB/8)   // 3328 dual-group mean blocks

typedef unsigned long long ull;

// Scratch (no cudaMalloc allowed -> __device__ globals)
__device__ float g_m1[M1 * ND];    // mean over S2 of hop-2 feats  [25600,256]
__device__ float g_m0[NB * ND];    // mean over S1 of hop-1 feats  [1024,256]
__device__ float g_g1[M1 * ND];    // layer-1 out, hop-1 set       [25600,256]
__device__ float g_g0[NB * ND];    // layer-1 out, batch set       [1024,256]
__device__ float g_Wc[512 * NC];   // collapsed layer2*head weights[512,64]
__device__ float g_bc[NC];         // collapsed bias               [64]
__device__ float g_Wx1T[NH * ND];  // Wx1^T, tf32-rounded [128,256]
__device__ float g_Wn1T[NH * ND];  // Wn1^T, tf32-rounded [128,256]

// ---- tf32 helpers (baseline sm_80 PTX; legal on compute_103) ---------------
__device__ __forceinline__ float tf32s(float x) {
    uint32_t u;
    asm("cvt.rna.tf32.f32 %0, %1;" : "=r"(u) : "f"(x));
    return __uint_as_float(u);
}
#define MMA_TF32(d, a, b)                                                  \
    asm volatile("mma.sync.aligned.m16n8k8.row.col.f32.tf32.tf32.f32 "    \
        "{%0,%1,%2,%3}, {%4,%5,%6,%7}, {%8,%9}, {%0,%1,%2,%3};"           \
        : "+f"((d)[0]), "+f"((d)[1]), "+f"((d)[2]), "+f"((d)[3])          \
        : "r"((a)[0]), "r"((a)[1]), "r"((a)[2]), "r"((a)[3]),             \
          "r"((b)[0]), "r"((b)[1]))

// ---- cp.async (baseline sm_80) ---------------------------------------------
#define CP_ASYNC16(saddr, gptr)                                            \
    asm volatile("cp.async.cg.shared.global [%0], [%1], 16;"               \
                 :: "r"(saddr), "l"(gptr) : "memory")
#define CP_COMMIT() asm volatile("cp.async.commit_group;" ::: "memory")
#define CP_WAIT(n)  asm volatile("cp.async.wait_group %0;" :: "n"(n) : "memory")

// ---------------------------------------------------------------------------
// Dual-group pipelined gather-mean (R12-proven). tf32-rounds the result so
// layer1 can consume m1/m0 without a cvt in its hot loop.
// ---------------------------------------------------------------------------
template<int F, bool HAS_IDS>
__device__ __forceinline__ void mean2_body(
    const float* __restrict__ src, const int* __restrict__ ids,
    float* __restrict__ dst, int ga, int gb)
{
    const int c = (threadIdx.x & 63) * 4;
    const long ba = (long)ga * F;
    const long bb = (long)gb * F;
    float4 accA = make_float4(0.f, 0.f, 0.f, 0.f);
    float4 accB = make_float4(0.f, 0.f, 0.f, 0.f);
    #pragma unroll
    for (int s = 0; s < F; ++s) {
        const int ra = HAS_IDS ? ids[ba + s] : (int)(ba + s);
        const int rb = HAS_IDS ? ids[bb + s] : (int)(bb + s);
        float4 ua = *(const float4*)&src[(size_t)ra * ND + c];
        float4 ub = *(const float4*)&src[(size_t)rb * ND + c];
        accA.x += ua.x; accA.y += ua.y; accA.z += ua.z; accA.w += ua.w;
        accB.x += ub.x; accB.y += ub.y; accB.z += ub.z; accB.w += ub.w;
    }
    constexpr float inv = 1.0f / (float)F;
    accA = make_float4(tf32s(accA.x * inv), tf32s(accA.y * inv),
                       tf32s(accA.z * inv), tf32s(accA.w * inv));
    accB = make_float4(tf32s(accB.x * inv), tf32s(accB.y * inv),
                       tf32s(accB.z * inv), tf32s(accB.w * inv));
    __stcs((float4*)&dst[(size_t)ga * ND + c], accA);
    __stcs((float4*)&dst[(size_t)gb * ND + c], accB);
}

// means + Wc/bc + tf32-W^T precompute. Grid = NMEAN2 + 35.
__global__ void __launch_bounds__(256) means_kernel(
    const float* __restrict__ feat,
    const int* __restrict__ ids1, const int* __restrict__ ids2,
    const float* __restrict__ Wx1, const float* __restrict__ Wn1,
    const float* __restrict__ Wx2, const float* __restrict__ bx2,
    const float* __restrict__ Wn2, const float* __restrict__ bn2,
    const float* __restrict__ Wfc, const float* __restrict__ bfc,
    float* __restrict__ m1, float* __restrict__ m0,
    float* __restrict__ Wc, float* __restrict__ bc,
    float* __restrict__ Wx1T, float* __restrict__ Wn1T)
{
    const int bx = blockIdx.x;
    const int t  = threadIdx.x;
    const int sub = t >> 6;
    if (bx < M1 / 8) {
        const int g = bx * 8 + sub * 2;
        mean2_body<NS2, true>(feat, ids2, m1, g, g + 1);
    } else if (bx < NMEAN2) {
        const int g = (bx - M1 / 8) * 8 + sub * 2;
        mean2_body<NS1, true>(feat, ids1, m0, g, g + 1);
    } else if (bx < NMEAN2 + 32) {
        const int R0 = (bx - NMEAN2) * 16;
        const int c  = t & 63;
        const int rg = t >> 6;
        const bool top = (R0 < 256);
        const float* W2   = top ? Wx2 : Wn2;
        const float* WfcH = Wfc + (top ? 0 : 128 * NC);
        const int rbase = (top ? R0 : R0 - 256) + rg * 4;
        float acc[4] = {0.f, 0.f, 0.f, 0.f};
        #pragma unroll 8
        for (int k = 0; k < 128; ++k) {
            float w = WfcH[(size_t)k * NC + c];
            #pragma unroll
            for (int i = 0; i < 4; ++i)
                acc[i] = fmaf(W2[(size_t)(rbase + i) * NH + k], w, acc[i]);
        }
        #pragma unroll
        for (int i = 0; i < 4; ++i)
            Wc[(size_t)(R0 + rg * 4 + i) * NC + c] = acc[i];
    } else if (bx == NMEAN2 + 32) {
        if (t < NC) {
            float acc = bfc[t];
            #pragma unroll 8
            for (int k = 0; k < 128; ++k) {
                acc = fmaf(bx2[k], Wfc[(size_t)k * NC + t], acc);
                acc = fmaf(bn2[k], Wfc[(size_t)(128 + k) * NC + t], acc);
            }
            bc[t] = acc;
        }
    } else {
        // transpose + pre-round to tf32 (consumed raw in layer1)
        const float* W = (bx == NMEAN2 + 33) ? Wx1 : Wn1;
        float* WT      = (bx == NMEAN2 + 33) ? Wx1T : Wn1T;
        for (int idx = t; idx < ND * NH; idx += 256) {
            int k = idx >> 7, n = idx & 127;
            WT[(size_t)n * ND + k] = tf32s(W[idx]);
        }
    }
}

// ---------------------------------------------------------------------------
// Layer 1 via mma.sync tf32 with cp.async double-buffered staging. Grid 416.
// CTA tile 128x128, K=256 in 8 chunks of 32. 8 warps: warp = 64m x 32n,
// 4x4 frags of m16n8k8. Smem rows stride 36 words (conflict-free LDS).
// No cvt in hot loop: B/m1/m0 pre-rounded; feat consumed as rz-truncated tf32.
// Dynamic smem: A0|B0|A1|B1 = 4*4608 words = 73728 B -> 2 CTAs/SM.
// ---------------------------------------------------------------------------
#define CHW 4608
__global__ void __launch_bounds__(256, 2) layer1_mma(
    const float* __restrict__ feat,
    const int* __restrict__ ids0, const int* __restrict__ ids1,
    const float* __restrict__ m1, const float* __restrict__ m0,
    const float* __restrict__ Wx1T, const float* __restrict__ bx1,
    const float* __restrict__ Wn1T, const float* __restrict__ bn1,
    float* __restrict__ g1, float* __restrict__ g0)
{
    extern __shared__ uint32_t sd[];
    uint32_t* Abuf[2] = { sd,            sd + 2 * CHW };
    uint32_t* Bbuf[2] = { sd + CHW,      sd + 3 * CHW };

    // branch decode
    const float* Asrc; const int* ids; const float* WT; const float* bias;
    float* C; int colOff, mbase;
    const int x = blockIdx.x;
    if (x < 200)      { Asrc = feat; ids = ids1; WT = Wx1T; bias = bx1; C = g1; colOff = 0;   mbase = x * 128; }
    else if (x < 400) { Asrc = m1;   ids = 0;    WT = Wn1T; bias = bn1; C = g1; colOff = 128; mbase = (x - 200) * 128; }
    else if (x < 408) { Asrc = feat; ids = ids0; WT = Wx1T; bias = bx1; C = g0; colOff = 0;   mbase = (x - 400) * 128; }
    else              { Asrc = m0;   ids = 0;    WT = Wn1T; bias = bn1; C = g0; colOff = 128; mbase = (x - 408) * 128; }

    const int t    = threadIdx.x;
    const int r    = t >> 1;            // staging row 0..127
    const int kh   = (t & 1) * 16;      // staging k half
    const int arow = ids ? ids[mbase + r] : (mbase + r);
    const float* ap = Asrc + (size_t)arow * ND + kh;
    const float* bp = WT + (size_t)r * ND + kh;
    const uint32_t dofb = (uint32_t)((r * 36 + kh) * 4);   // byte offset
    uint32_t sA[2], sB[2];
    #pragma unroll
    for (int p = 0; p < 2; ++p) {
        sA[p] = (uint32_t)__cvta_generic_to_shared(Abuf[p]) + dofb;
        sB[p] = (uint32_t)__cvta_generic_to_shared(Bbuf[p]) + dofb;
    }

    const int wid = t >> 5, lane = t & 31;
    const int g = lane >> 2, c = lane & 3;
    const int m0w = (wid & 1) * 64;
    const int n0w = (wid >> 1) * 32;

    float acc[4][4][4];
    #pragma unroll
    for (int mf = 0; mf < 4; ++mf)
        #pragma unroll
        for (int nf = 0; nf < 4; ++nf)
            #pragma unroll
            for (int i = 0; i < 4; ++i) acc[mf][nf][i] = 0.f;

    // prologue: stage chunk 0 into buffer 0
    #pragma unroll
    for (int i = 0; i < 4; ++i) {
        CP_ASYNC16(sA[0] + 16 * i, ap + 4 * i);
        CP_ASYNC16(sB[0] + 16 * i, bp + 4 * i);
    }
    CP_COMMIT();

    #pragma unroll 1
    for (int ch = 0; ch < 8; ++ch) {
        const int p = ch & 1;
        // stage chunk ch+1 into the idle buffer
        if (ch < 7) {
            const int k0 = (ch + 1) * 32;
            #pragma unroll
            for (int i = 0; i < 4; ++i) {
                CP_ASYNC16(sA[1 - p] + 16 * i, ap + k0 + 4 * i);
                CP_ASYNC16(sB[1 - p] + 16 * i, bp + k0 + 4 * i);
            }
            CP_COMMIT();
            CP_WAIT(1);         // chunk ch's group complete (own copies)
        } else {
            CP_WAIT(0);
        }
        __syncthreads();        // all threads' copies visible

        const uint32_t* As = Abuf[p];
        const uint32_t* Bs = Bbuf[p];
        #pragma unroll
        for (int kb = 0; kb < 32; kb += 8) {
            uint32_t a[4][4], b[4][2];
            #pragma unroll
            for (int mf = 0; mf < 4; ++mf) {
                const int base = (m0w + mf * 16 + g) * 36 + kb + c;
                a[mf][0] = As[base];
                a[mf][1] = As[base + 8 * 36];
                a[mf][2] = As[base + 4];
                a[mf][3] = As[base + 8 * 36 + 4];
            }
            #pragma unroll
            for (int nf = 0; nf < 4; ++nf) {
                const int bb = (n0w + nf * 8 + g) * 36 + kb + c;
                b[nf][0] = Bs[bb];
                b[nf][1] = Bs[bb + 4];
            }
            #pragma unroll
            for (int mf = 0; mf < 4; ++mf)
                #pragma unroll
                for (int nf = 0; nf < 4; ++nf)
                    MMA_TF32(acc[mf][nf], a[mf], b[nf]);
        }
        if (ch < 7) __syncthreads();   // buf p is rewritten next iteration
    }

    // epilogue: bias + relu, st.v2 per frag row
    #pragma unroll
    for (int nf = 0; nf < 4; ++nf) {
        const int bcol = n0w + nf * 8 + c * 2;
        const float b0 = bias[bcol], b1 = bias[bcol + 1];
        #pragma unroll
        for (int mf = 0; mf < 4; ++mf) {
            const int m = mbase + m0w + mf * 16 + g;
            float2 v0 = make_float2(fmaxf(acc[mf][nf][0] + b0, 0.f),
                                    fmaxf(acc[mf][nf][1] + b1, 0.f));
            float2 v1 = make_float2(fmaxf(acc[mf][nf][2] + b0, 0.f),
                                    fmaxf(acc[mf][nf][3] + b1, 0.f));
            *(float2*)&C[(size_t)m * ND + colOff + bcol]       = v0;
            *(float2*)&C[(size_t)(m + 8) * ND + colOff + bcol] = v1;
        }
    }
}

// ---------------------------------------------------------------------------
// Final GEMM with fused g1-mean: out[1024,64] = [g0 | mean25(g1)] @ Wc + bc.
// ---------------------------------------------------------------------------
__global__ void __launch_bounds__(256) final_kernel(
    const float* __restrict__ g0, const float* __restrict__ g1,
    const float* __restrict__ Wc, const float* __restrict__ bc,
    float* __restrict__ out)
{
    __shared__ float As[8 * 520];      // [row][k 0..511], pad 8
    __shared__ float Ws[64 * 68];      // [k][c], pad 4

    const int t  = threadIdx.x;
    const int m0 = blockIdx.x * 8;

    #pragma unroll
    for (int i = 0; i < 2; ++i) {
        int s = t + 256 * i;
        int row = s >> 6, k4 = (s & 63) * 4;
        *(float4*)&As[row * 520 + k4] =
            *(const float4*)&g0[(size_t)(m0 + row) * ND + k4];
    }
    {
        const int c4 = (t & 63) * 4;
        const int gs = t >> 6;
        #pragma unroll
        for (int h = 0; h < 2; ++h) {
            const int grp = gs + 4 * h;
            const float* src = g1 + (size_t)(m0 + grp) * NS1 * ND + c4;
            float4 acc = make_float4(0.f, 0.f, 0.f, 0.f);
            #pragma unroll
            for (int s = 0; s < NS1; ++s) {
                float4 u = *(const float4*)(src + (size_t)s * ND);
                acc.x += u.x; acc.y += u.y; acc.z += u.z; acc.w += u.w;
            }
            constexpr float inv = 1.0f / (float)NS1;
            acc.x *= inv; acc.y *= inv; acc.z *= inv; acc.w *= inv;
            *(float4*)&As[grp * 520 + 256 + c4] = acc;
        }
    }
    float4 breg[4];
    #pragma unroll
    for (int i = 0; i < 4; ++i) {
        int s = t + 256 * i;
        int kk = s >> 4, c4 = (s & 15) * 4;
        breg[i] = *(const float4*)&Wc[(size_t)kk * NC + c4];
    }
    __syncthreads();

    const int c  = t & 63;
    const int r0 = (t >> 6) * 2;
    float acc0 = 0.f, acc1 = 0.f;

    #pragma unroll 1
    for (int j = 0; j < 8; ++j) {
        #pragma unroll
        for (int i = 0; i < 4; ++i) {
            int s = t + 256 * i;
            int kk = s >> 4, c4 = (s & 15) * 4;
            *(float4*)&Ws[kk * 68 + c4] = breg[i];
        }
        __syncthreads();
        if (j < 7) {
            #pragma unroll
            for (int i = 0; i < 4; ++i) {
                int s = t + 256 * i;
                int kk = (s >> 4) + (j + 1) * 64, c4 = (s & 15) * 4;
                breg[i] = *(const float4*)&Wc[(size_t)kk * NC + c4];
            }
        }
        const float* a0p = &As[r0 * 520 + j * 64];
        const float* a1p = &As[(r0 + 1) * 520 + j * 64];
        #pragma unroll
        for (int k = 0; k < 64; ++k) {
            float w = Ws[k * 68 + c];
            acc0 = fmaf(a0p[k], w, acc0);
            acc1 = fmaf(a1p[k], w, acc1);
        }
        __syncthreads();
    }

    float b = bc[c];
    out[(size_t)(m0 + r0) * NC + c]     = acc0 + b;
    out[(size_t)(m0 + r0 + 1) * NC + c] = acc1 + b;
}

// ---------------------------------------------------------------------------
extern "C" void kernel_launch(void* const* d_in, const int* in_sizes, int n_in,
                              void* d_out, int out_size)
{
    const int*   ids0 = (const int*)  d_in[0];
    const int*   ids1 = (const int*)  d_in[1];
    const int*   ids2 = (const int*)  d_in[2];
    const float* feat = (const float*)d_in[3];
    const float* Wx1  = (const float*)d_in[4];
    const float* bx1  = (const float*)d_in[5];
    const float* Wn1  = (const float*)d_in[6];
    const float* bn1  = (const float*)d_in[7];
    const float* Wx2  = (const float*)d_in[8];
    const float* bx2  = (const float*)d_in[9];
    const float* Wn2  = (const float*)d_in[10];
    const float* bn2  = (const float*)d_in[11];
    const float* Wfc  = (const float*)d_in[12];
    const float* bfc  = (const float*)d_in[13];
    float* out = (float*)d_out;

    float *m1, *m0, *g1, *g0, *Wc, *bc, *Wx1T, *Wn1T;
    cudaGetSymbolAddress((void**)&m1, g_m1);
    cudaGetSymbolAddress((void**)&m0, g_m0);
    cudaGetSymbolAddress((void**)&g1, g_g1);
    cudaGetSymbolAddress((void**)&g0, g_g0);
    cudaGetSymbolAddress((void**)&Wc, g_Wc);
    cudaGetSymbolAddress((void**)&bc, g_bc);
    cudaGetSymbolAddress((void**)&Wx1T, g_Wx1T);
    cudaGetSymbolAddress((void**)&Wn1T, g_Wn1T);

    static bool attr_set = false;
    if (!attr_set) {
        cudaFuncSetAttribute(layer1_mma,
                             cudaFuncAttributeMaxDynamicSharedMemorySize,
                             4 * CHW * 4);
        attr_set = true;
    }

    // 1) gather means (dual-group, R12-proven) + Wc/bc/tf32-W^T precompute
    means_kernel<<<NMEAN2 + 35, 256>>>(
        feat, ids1, ids2, Wx1, Wn1, Wx2, bx2, Wn2, bn2, Wfc, bfc,
        m1, m0, Wc, bc, Wx1T, Wn1T);

    // 2) layer 1: four branch GEMMs, cp.async double-buffered tf32 MMA
    layer1_mma<<<416, 256, 4 * CHW * 4>>>(
        feat, ids0, ids1, m1, m0, Wx1T, bx1, Wn1T, bn1, g1, g0);

    // 3) fused g1-mean + collapsed layer2+head GEMM
    final_kernel<<<NB / 8, 256>>>(g0, g1, Wc, bc, out);
}

// round 15
// speedup vs baseline: 1.1325x; 1.1264x over previous
#include <cuda_runtime.h>
#include <cuda_bf16.h>
#include <cstdint>

// Problem constants (fixed by the reference)
#define NB   1024      // batch
#define NS1  25        // hop-1 fanout
#define NS2  10        // hop-2 fanout
#define ND   256       // feature dim
#define NH   128       // per-branch hidden
#define NC   64        // classes
#define M1   (NB*NS1)  // 25600
#define NPRE 35              // precompute blocks (32 Wc + 1 bc + 2 WT)
#define NM0B (NB/8)          // 128 m0 dual-group blocks
#define NM1B (M1/8)          // 3200 m1 dual-group blocks
#define NGRID (NPRE + NM0B + NM1B)   // 3363

typedef unsigned long long ull;

// Scratch (no cudaMalloc allowed -> __device__ globals)
__device__ float g_m1[M1 * ND];    // mean over S2 of hop-2 feats  [25600,256]
__device__ float g_m0[NB * ND];    // mean over S1 of hop-1 feats  [1024,256]
__device__ float g_g1[M1 * ND];    // layer-1 out, hop-1 set       [25600,256]
__device__ float g_g0[NB * ND];    // layer-1 out, batch set       [1024,256]
__device__ float g_Wc[512 * NC];   // collapsed layer2*head weights[512,64]
__device__ float g_bc[NC];         // collapsed bias               [64]
__device__ float g_Wx1T[NH * ND];  // Wx1^T, tf32-rounded [128,256]
__device__ float g_Wn1T[NH * ND];  // Wn1^T, tf32-rounded [128,256]

// ---- tf32 helpers (baseline sm_80 PTX; legal on compute_103) ---------------
__device__ __forceinline__ uint4 tf32x4(float4 v) {
    uint4 u;
    asm("cvt.rna.tf32.f32 %0, %1;" : "=r"(u.x) : "f"(v.x));
    asm("cvt.rna.tf32.f32 %0, %1;" : "=r"(u.y) : "f"(v.y));
    asm("cvt.rna.tf32.f32 %0, %1;" : "=r"(u.z) : "f"(v.z));
    asm("cvt.rna.tf32.f32 %0, %1;" : "=r"(u.w) : "f"(v.w));
    return u;
}
__device__ __forceinline__ float tf32s(float x) {
    uint32_t u;
    asm("cvt.rna.tf32.f32 %0, %1;" : "=r"(u) : "f"(x));
    return __uint_as_float(u);
}
#define MMA_TF32(d, a, b)                                                  \
    asm volatile("mma.sync.aligned.m16n8k8.row.col.f32.tf32.tf32.f32 "    \
        "{%0,%1,%2,%3}, {%4,%5,%6,%7}, {%8,%9}, {%0,%1,%2,%3};"           \
        : "+f"((d)[0]), "+f"((d)[1]), "+f"((d)[2]), "+f"((d)[3])          \
        : "r"((a)[0]), "r"((a)[1]), "r"((a)[2]), "r"((a)[3]),             \
          "r"((b)[0]), "r"((b)[1]))

// ---------------------------------------------------------------------------
// Dual-group pipelined gather-mean (R12-proven). tf32-rounds outputs.
// ---------------------------------------------------------------------------
template<int F, bool HAS_IDS>
__device__ __forceinline__ void mean2_body(
    const float* __restrict__ src, const int* __restrict__ ids,
    float* __restrict__ dst, int ga, int gb)
{
    const int c = (threadIdx.x & 63) * 4;
    const long ba = (long)ga * F;
    const long bb = (long)gb * F;
    float4 accA = make_float4(0.f, 0.f, 0.f, 0.f);
    float4 accB = make_float4(0.f, 0.f, 0.f, 0.f);
    #pragma unroll
    for (int s = 0; s < F; ++s) {
        const int ra = HAS_IDS ? ids[ba + s] : (int)(ba + s);
        const int rb = HAS_IDS ? ids[bb + s] : (int)(bb + s);
        float4 ua = *(const float4*)&src[(size_t)ra * ND + c];
        float4 ub = *(const float4*)&src[(size_t)rb * ND + c];
        accA.x += ua.x; accA.y += ua.y; accA.z += ua.z; accA.w += ua.w;
        accB.x += ub.x; accB.y += ub.y; accB.z += ub.z; accB.w += ub.w;
    }
    constexpr float inv = 1.0f / (float)F;
    accA = make_float4(tf32s(accA.x * inv), tf32s(accA.y * inv),
                       tf32s(accA.z * inv), tf32s(accA.w * inv));
    accB = make_float4(tf32s(accB.x * inv), tf32s(accB.y * inv),
                       tf32s(accB.z * inv), tf32s(accB.w * inv));
    __stcs((float4*)&dst[(size_t)ga * ND + c], accA);
    __stcs((float4*)&dst[(size_t)gb * ND + c], accB);
}

// ---------------------------------------------------------------------------
// means + Wc/bc + tf32-W^T precompute. Grid = NGRID.
// LONG-RUNNING blocks (precompute, F=25 m0) placed FIRST so they start in
// wave 1; the bulk F=10 m1 blocks fill in behind (kills the slow tail).
// ---------------------------------------------------------------------------
__global__ void __launch_bounds__(256) means_kernel(
    const float* __restrict__ feat,
    const int* __restrict__ ids1, const int* __restrict__ ids2,
    const float* __restrict__ Wx1, const float* __restrict__ Wn1,
    const float* __restrict__ Wx2, const float* __restrict__ bx2,
    const float* __restrict__ Wn2, const float* __restrict__ bn2,
    const float* __restrict__ Wfc, const float* __restrict__ bfc,
    float* __restrict__ m1, float* __restrict__ m0,
    float* __restrict__ Wc, float* __restrict__ bc,
    float* __restrict__ Wx1T, float* __restrict__ Wn1T)
{
    const int bx = blockIdx.x;
    const int t  = threadIdx.x;
    const int sub = t >> 6;
    if (bx < 32) {
        // Wc rows [R0, R0+16)
        const int R0 = bx * 16;
        const int c  = t & 63;
        const int rg = t >> 6;
        const bool top = (R0 < 256);
        const float* W2   = top ? Wx2 : Wn2;
        const float* WfcH = Wfc + (top ? 0 : 128 * NC);
        const int rbase = (top ? R0 : R0 - 256) + rg * 4;
        float acc[4] = {0.f, 0.f, 0.f, 0.f};
        #pragma unroll 8
        for (int k = 0; k < 128; ++k) {
            float w = WfcH[(size_t)k * NC + c];
            #pragma unroll
            for (int i = 0; i < 4; ++i)
                acc[i] = fmaf(W2[(size_t)(rbase + i) * NH + k], w, acc[i]);
        }
        #pragma unroll
        for (int i = 0; i < 4; ++i)
            Wc[(size_t)(R0 + rg * 4 + i) * NC + c] = acc[i];
    } else if (bx == 32) {
        if (t < NC) {
            float acc = bfc[t];
            #pragma unroll 8
            for (int k = 0; k < 128; ++k) {
                acc = fmaf(bx2[k], Wfc[(size_t)k * NC + t], acc);
                acc = fmaf(bn2[k], Wfc[(size_t)(128 + k) * NC + t], acc);
            }
            bc[t] = acc;
        }
    } else if (bx < NPRE) {
        // transpose + pre-round to tf32
        const float* W = (bx == 33) ? Wx1 : Wn1;
        float* WT      = (bx == 33) ? Wx1T : Wn1T;
        for (int idx = t; idx < ND * NH; idx += 256) {
            int k = idx >> 7, n = idx & 127;
            WT[(size_t)n * ND + k] = tf32s(W[idx]);
        }
    } else if (bx < NPRE + NM0B) {
        const int g = (bx - NPRE) * 8 + sub * 2;
        mean2_body<NS1, true>(feat, ids1, m0, g, g + 1);
    } else {
        const int g = (bx - NPRE - NM0B) * 8 + sub * 2;
        mean2_body<NS2, true>(feat, ids2, m1, g, g + 1);
    }
}

// ---------------------------------------------------------------------------
// Layer 1 via mma.sync tf32 (R12-proven single-buffer version). Grid 416.
// CTA tile 128x128, K=256 in 8 chunks of 32. 8 warps: warp = 64m x 32n,
// 4x4 frags of m16n8k8. Smem rows stride 36 words (conflict-free LDS).
// ---------------------------------------------------------------------------
__global__ void __launch_bounds__(256, 2) layer1_mma(
    const float* __restrict__ feat,
    const int* __restrict__ ids0, const int* __restrict__ ids1,
    const float* __restrict__ m1, const float* __restrict__ m0,
    const float* __restrict__ Wx1T, const float* __restrict__ bx1,
    const float* __restrict__ Wn1T, const float* __restrict__ bn1,
    float* __restrict__ g1, float* __restrict__ g0)
{
    __shared__ uint32_t As[128 * 36];   // 18KB, [row][k] stride 36
    __shared__ uint32_t Bs[128 * 36];   // 18KB, [n][k]  stride 36

    // branch decode
    const float* Asrc; const int* ids; const float* WT; const float* bias;
    float* C; int colOff, mbase;
    const int x = blockIdx.x;
    if (x < 200)      { Asrc = feat; ids = ids1; WT = Wx1T; bias = bx1; C = g1; colOff = 0;   mbase = x * 128; }
    else if (x < 400) { Asrc = m1;   ids = 0;    WT = Wn1T; bias = bn1; C = g1; colOff = 128; mbase = (x - 200) * 128; }
    else if (x < 408) { Asrc = feat; ids = ids0; WT = Wx1T; bias = bx1; C = g0; colOff = 0;   mbase = (x - 400) * 128; }
    else              { Asrc = m0;   ids = 0;    WT = Wn1T; bias = bn1; C = g0; colOff = 128; mbase = (x - 408) * 128; }

    const int t    = threadIdx.x;
    const int r    = t >> 1;            // staging row 0..127
    const int kh   = (t & 1) * 16;      // staging k half
    const int arow = ids ? ids[mbase + r] : (mbase + r);
    const float* ap = Asrc + (size_t)arow * ND + kh;
    const float* bp = WT + (size_t)r * ND + kh;
    uint32_t* Ad = &As[r * 36 + kh];
    uint32_t* Bd = &Bs[r * 36 + kh];

    const int wid = t >> 5, lane = t & 31;
    const int g = lane >> 2, c = lane & 3;
    const int m0w = (wid & 1) * 64;
    const int n0w = (wid >> 1) * 32;

    float acc[4][4][4];
    #pragma unroll
    for (int mf = 0; mf < 4; ++mf)
        #pragma unroll
        for (int nf = 0; nf < 4; ++nf)
            #pragma unroll
            for (int i = 0; i < 4; ++i) acc[mf][nf][i] = 0.f;

    #pragma unroll 1
    for (int ch = 0; ch < 8; ++ch) {
        const int k0 = ch * 32;
        float4 av0 = *(const float4*)(ap + k0);
        float4 av1 = *(const float4*)(ap + k0 + 4);
        float4 av2 = *(const float4*)(ap + k0 + 8);
        float4 av3 = *(const float4*)(ap + k0 + 12);
        float4 bv0 = *(const float4*)(bp + k0);
        float4 bv1 = *(const float4*)(bp + k0 + 4);
        float4 bv2 = *(const float4*)(bp + k0 + 8);
        float4 bv3 = *(const float4*)(bp + k0 + 12);
        if (ch) __syncthreads();
        *(uint4*)(Ad + 0)  = tf32x4(av0);
        *(uint4*)(Ad + 4)  = tf32x4(av1);
        *(uint4*)(Ad + 8)  = tf32x4(av2);
        *(uint4*)(Ad + 12) = tf32x4(av3);
        *(uint4*)(Bd + 0)  = tf32x4(bv0);
        *(uint4*)(Bd + 4)  = tf32x4(bv1);
        *(uint4*)(Bd + 8)  = tf32x4(bv2);
        *(uint4*)(Bd + 12) = tf32x4(bv3);
        __syncthreads();

        #pragma unroll
        for (int kb = 0; kb < 32; kb += 8) {
            uint32_t a[4][4], b[4][2];
            #pragma unroll
            for (int mf = 0; mf < 4; ++mf) {
                const int base = (m0w + mf * 16 + g) * 36 + kb + c;
                a[mf][0] = As[base];
                a[mf][1] = As[base + 8 * 36];
                a[mf][2] = As[base + 4];
                a[mf][3] = As[base + 8 * 36 + 4];
            }
            #pragma unroll
            for (int nf = 0; nf < 4; ++nf) {
                const int bb = (n0w + nf * 8 + g) * 36 + kb + c;
                b[nf][0] = Bs[bb];
                b[nf][1] = Bs[bb + 4];
            }
            #pragma unroll
            for (int mf = 0; mf < 4; ++mf)
                #pragma unroll
                for (int nf = 0; nf < 4; ++nf)
                    MMA_TF32(acc[mf][nf], a[mf], b[nf]);
        }
    }

    // epilogue: bias + relu, st.v2 per frag row
    #pragma unroll
    for (int nf = 0; nf < 4; ++nf) {
        const int bcol = n0w + nf * 8 + c * 2;
        const float b0 = bias[bcol], b1 = bias[bcol + 1];
        #pragma unroll
        for (int mf = 0; mf < 4; ++mf) {
            const int m = mbase + m0w + mf * 16 + g;
            float2 v0 = make_float2(fmaxf(acc[mf][nf][0] + b0, 0.f),
                                    fmaxf(acc[mf][nf][1] + b1, 0.f));
            float2 v1 = make_float2(fmaxf(acc[mf][nf][2] + b0, 0.f),
                                    fmaxf(acc[mf][nf][3] + b1, 0.f));
            *(float2*)&C[(size_t)m * ND + colOff + bcol]       = v0;
            *(float2*)&C[(size_t)(m + 8) * ND + colOff + bcol] = v1;
        }
    }
}

// ---------------------------------------------------------------------------
// Final GEMM with fused g1-mean, 512 threads (2x warps to hide mean latency):
//   out[1024,64] = [g0 | mean25(g1)] @ Wc[512,64] + bc.   grid 128, 8 rows.
// ---------------------------------------------------------------------------
__global__ void __launch_bounds__(512) final_kernel(
    const float* __restrict__ g0, const float* __restrict__ g1,
    const float* __restrict__ Wc, const float* __restrict__ bc,
    float* __restrict__ out)
{
    __shared__ float As[8 * 520];      // [row][k 0..511], pad 8
    __shared__ float Ws[64 * 68];      // [k][c], pad 4

    const int t  = threadIdx.x;
    const int m0 = blockIdx.x * 8;

    // ---- stage g0 half: 8 rows x 256 k = 512 float4 (one per thread) ----
    {
        int row = t >> 6, k4 = (t & 63) * 4;
        *(float4*)&As[row * 520 + k4] =
            *(const float4*)&g0[(size_t)(m0 + row) * ND + k4];
    }
    // ---- compute gm half: 8 groups x 64 float4 slots = 512 threads ----
    {
        const int c4 = (t & 63) * 4;
        const int grp = t >> 6;              // 0..7
        const float* src = g1 + (size_t)(m0 + grp) * NS1 * ND + c4;
        float4 acc = make_float4(0.f, 0.f, 0.f, 0.f);
        #pragma unroll
        for (int s = 0; s < NS1; ++s) {
            float4 u = *(const float4*)(src + (size_t)s * ND);
            acc.x += u.x; acc.y += u.y; acc.z += u.z; acc.w += u.w;
        }
        constexpr float inv = 1.0f / (float)NS1;
        acc.x *= inv; acc.y *= inv; acc.z *= inv; acc.w *= inv;
        *(float4*)&As[grp * 520 + 256 + c4] = acc;
    }
    // ---- prefetch Wc chunk 0 (64x64 = 1024 float4, 2 per thread) ----
    float4 breg[2];
    #pragma unroll
    for (int i = 0; i < 2; ++i) {
        int s = t + 512 * i;
        int kk = s >> 4, c4 = (s & 15) * 4;
        breg[i] = *(const float4*)&Wc[(size_t)kk * NC + c4];
    }
    __syncthreads();

    const int c = t & 63;
    const int r = t >> 6;                    // 0..7, one output per thread
    float acc0 = 0.f;

    #pragma unroll 1
    for (int j = 0; j < 8; ++j) {
        #pragma unroll
        for (int i = 0; i < 2; ++i) {
            int s = t + 512 * i;
            int kk = s >> 4, c4 = (s & 15) * 4;
            *(float4*)&Ws[kk * 68 + c4] = breg[i];
        }
        __syncthreads();
        if (j < 7) {
            #pragma unroll
            for (int i = 0; i < 2; ++i) {
                int s = t + 512 * i;
                int kk = (s >> 4) + (j + 1) * 64, c4 = (s & 15) * 4;
                breg[i] = *(const float4*)&Wc[(size_t)kk * NC + c4];
            }
        }
        const float* a0p = &As[r * 520 + j * 64];
        #pragma unroll
        for (int k = 0; k < 64; ++k)
            acc0 = fmaf(a0p[k], Ws[k * 68 + c], acc0);
        __syncthreads();
    }

    out[(size_t)(m0 + r) * NC + c] = acc0 + bc[c];
}

// ---------------------------------------------------------------------------
extern "C" void kernel_launch(void* const* d_in, const int* in_sizes, int n_in,
                              void* d_out, int out_size)
{
    const int*   ids0 = (const int*)  d_in[0];
    const int*   ids1 = (const int*)  d_in[1];
    const int*   ids2 = (const int*)  d_in[2];
    const float* feat = (const float*)d_in[3];
    const float* Wx1  = (const float*)d_in[4];
    const float* bx1  = (const float*)d_in[5];
    const float* Wn1  = (const float*)d_in[6];
    const float* bn1  = (const float*)d_in[7];
    const float* Wx2  = (const float*)d_in[8];
    const float* bx2  = (const float*)d_in[9];
    const float* Wn2  = (const float*)d_in[10];
    const float* bn2  = (const float*)d_in[11];
    const float* Wfc  = (const float*)d_in[12];
    const float* bfc  = (const float*)d_in[13];
    float* out = (float*)d_out;

    float *m1, *m0, *g1, *g0, *Wc, *bc, *Wx1T, *Wn1T;
    cudaGetSymbolAddress((void**)&m1, g_m1);
    cudaGetSymbolAddress((void**)&m0, g_m0);
    cudaGetSymbolAddress((void**)&g1, g_g1);
    cudaGetSymbolAddress((void**)&g0, g_g0);
    cudaGetSymbolAddress((void**)&Wc, g_Wc);
    cudaGetSymbolAddress((void**)&bc, g_bc);
    cudaGetSymbolAddress((void**)&Wx1T, g_Wx1T);
    cudaGetSymbolAddress((void**)&Wn1T, g_Wn1T);

    // 1) gather means (slow blocks first) + Wc/bc/tf32-W^T precompute
    means_kernel<<<NGRID, 256>>>(
        feat, ids1, ids2, Wx1, Wn1, Wx2, bx2, Wn2, bn2, Wfc, bfc,
        m1, m0, Wc, bc, Wx1T, Wn1T);

    // 2) layer 1: four branch GEMMs on tf32 tensor cores (R12 version)
    layer1_mma<<<416, 256>>>(
        feat, ids0, ids1, m1, m0, Wx1T, bx1, Wn1T, bn1, g1, g0);

    // 3) fused g1-mean + collapsed layer2+head GEMM (512 threads)
    final_kernel<<<NB / 8, 512>>>(g0, g1, Wc, bc, out);
}